// round 13
// baseline (speedup 1.0000x reference)
#include <cuda_runtime.h>
#include <cstdint>

// GCNADP: adj = relu(tanh(2 * tanh(2*nv1) @ tanh(2*nv2)^T)); top-20 per row of
// adj + 0.01*noise; emit E=[src;dst] and HEW, all as float32.
//
// Plateau filter: XLA tanh clamps at |x|=7.90531..., so ~20% of adj entries
// per row equal the same plateau constant c_plat (max attainable adj). Pivot
// screen (R12): survivors = {score > c_plat + 0.0098}; >=20 survivors =>
// top-20 subset of survivors, EXACT by key order.
//
// R13: screen BEFORE scoring. survivor => 0.01u > 0.0098 => u > 0.98 (exact:
// adj <= c_plat and fadd/fmul monotone). Phase 1 builds the full u>0.955 list
// (fallback only) plus a hot u>0.98 list (~165/row); phase 2 scores only the
// hot list (55% less staging/scoring L1 traffic). Rare rows (<20 or >64
// survivors, or hot overflow) re-score the full list and take the exact
// all-pairs fallback.

#define KK    20
#define MAXC  512
#define TAU   0.955f
#define HOT   0.98f
#define MAXN  8192
#define DVEC  40
#define BATCH 128
#define ESTR  44   // padded smem row stride in floats (16B multiple: 176B)
#define SMAX  64   // survivor list capacity
#define HMAX  256  // hot list capacity

__device__ __align__(16) float g_DE[MAXN * DVEC];
__device__ __align__(16) float g_EE[MAXN * DVEC];

__device__ __forceinline__ unsigned smem_u32(const void* p) {
    unsigned a;
    asm("{ .reg .u64 t; cvta.to.shared.u64 t, %1; cvt.u32.u64 %0, t; }"
        : "=r"(a) : "l"(p));
    return a;
}
__device__ __forceinline__ void cp_async16(unsigned dst, const void* src) {
    asm volatile("cp.async.ca.shared.global [%0], [%1], 16;"
                 :: "r"(dst), "l"(src));
}

// XLA EmitFastTanh (f32): clamp to +-7.90531110763549805, rational P7/Q4 with
// plain (non-contracted) mul/add, passthrough for |x| < 4e-4, IEEE division.
__device__ __forceinline__ float xla_tanh(float x) {
    float ax = fabsf(x);
    float xc = fminf(fmaxf(x, -7.90531110763549805f), 7.90531110763549805f);
    float x2 = __fmul_rn(xc, xc);
    float p = __fadd_rn(__fmul_rn(x2, -2.76076847742355e-16f), 2.00018790482477e-13f);
    p = __fadd_rn(__fmul_rn(x2, p), -8.60467152213735e-11f);
    p = __fadd_rn(__fmul_rn(x2, p),  5.12229709037114e-08f);
    p = __fadd_rn(__fmul_rn(x2, p),  1.48572235717979e-05f);
    p = __fadd_rn(__fmul_rn(x2, p),  6.37261928875436e-04f);
    p = __fadd_rn(__fmul_rn(x2, p),  4.89352455891786e-03f);
    p = __fmul_rn(xc, p);
    float q = __fadd_rn(__fmul_rn(x2, 1.19825839466702e-06f), 1.18534705686654e-04f);
    q = __fadd_rn(__fmul_rn(x2, q), 2.26843463243900e-03f);
    q = __fadd_rn(__fmul_rn(x2, q), 4.89352518554385e-03f);
    float r = __fdiv_rn(p, q);
    return (ax < 4.0e-4f) ? x : r;
}

__global__ void prep_kernel(const float* __restrict__ v1,
                            const float* __restrict__ v2, int n) {
    int i = blockIdx.x * blockDim.x + threadIdx.x;
    if (i < n) {
        g_DE[i] = xla_tanh(__fmul_rn(2.0f, v1[i]));
        g_EE[i] = xla_tanh(__fmul_rn(2.0f, v2[i]));
    }
}

// Score `count` candidates from `list`: stage each candidate's 160B EE row
// into smem via coalesced 16B cp.async, then one thread per candidate does
// the dot40 + tanh + relu + noise (all rounding identical to R6/R8).
// Writes keys[i] = [score_bits:32 | N-1-j:32] and adjs[i]. Block-uniform.
__device__ __forceinline__ void score_list(
    const unsigned long long* __restrict__ list, int count,
    unsigned long long* __restrict__ keys, float* __restrict__ adjs,
    const float* __restrict__ s_de, float* __restrict__ s_ee,
    unsigned ee_base, int tid, int N) {
    int nb = (count + BATCH - 1) / BATCH;
    for (int b = 0; b < nb; b++) {
        int c0 = b * BATCH;
        int bc = min(BATCH, count - c0);
        {
            int cl = tid >> 1, q0 = tid & 1;
            if (cl < bc) {
                int j = (int)(unsigned)list[c0 + cl];
                const float* src = g_EE + j * DVEC;
                unsigned dst = ee_base + (unsigned)(cl * ESTR) * 4u;
#pragma unroll
                for (int i = 0; i < 5; i++) {
                    int q = q0 + i * 2;
                    cp_async16(dst + (unsigned)q * 16u, src + q * 4);
                }
            }
        }
        asm volatile("cp.async.commit_group;" ::: "memory");
        asm volatile("cp.async.wait_group 0;" ::: "memory");
        __syncthreads();
        if (tid < bc) {
            int c = c0 + tid;
            unsigned long long cd = list[c];
            int j = (int)(unsigned)cd;
            float u = __uint_as_float((unsigned)(cd >> 32));
            const float4* e = reinterpret_cast<const float4*>(s_ee + tid * ESTR);
            float s = 0.0f;
#pragma unroll
            for (int q2 = 0; q2 < DVEC / 4; q2++) {
                float4 ev = e[q2];
                s = fmaf(s_de[q2 * 4 + 0], ev.x, s);
                s = fmaf(s_de[q2 * 4 + 1], ev.y, s);
                s = fmaf(s_de[q2 * 4 + 2], ev.z, s);
                s = fmaf(s_de[q2 * 4 + 3], ev.w, s);
            }
            float t   = xla_tanh(__fmul_rn(2.0f, s));
            float adj = fmaxf(t, 0.0f);
            float score = __fadd_rn(adj, __fmul_rn(0.01f, u));  // >= 0
            adjs[c] = adj;
            keys[c] = (((unsigned long long)__float_as_uint(score)) << 32)
                    | (unsigned)(N - 1 - j);
        }
        __syncthreads();
    }
}

// One block per row: stream row -> full + hot candidate lists -> score hot ->
// pivot screen -> tiny exact rank (rare fallback: score+rank full) -> write.
__global__ __launch_bounds__(256, 6) void row_kernel(
    const float* __restrict__ noise, float* __restrict__ out,
    int N, int B, long long out_size) {
    int row = blockIdx.x;
    int tid = threadIdx.x;

    __shared__ alignas(16) float s_ee[BATCH * ESTR];  // staged EE rows (22KB)
    __shared__ alignas(16) float s_de[DVEC];
    __shared__ int   s_cnt, s_hcnt, s_scnt;
    __shared__ unsigned long long s_cand[MAXC];       // full list [u:32|j:32]
    __shared__ unsigned long long s_hot[HMAX];        // hot list  (u > 0.98)
    __shared__ unsigned long long s_key[MAXC];
    __shared__ float s_adj[MAXC];
    __shared__ unsigned long long s_skey[SMAX];
    __shared__ float s_sadj[SMAX];
    __shared__ int   sel_j[KK];
    __shared__ float sel_w[KK];
    __shared__ int   srt_j[KK];
    __shared__ float srt_w[KK];

    if (tid < DVEC) s_de[tid] = g_DE[row * DVEC + tid];
    if (tid == 0) { s_cnt = 0; s_hcnt = 0; s_scnt = 0; }
    __syncthreads();

    // Phase 1: stream this row (two rounds of 4 float4/thread). Push u > TAU
    // to the full list (fallback only) and u > HOT to the hot list.
    {
        const float4* nrow =
            reinterpret_cast<const float4*>(noise + (size_t)row * N);
#pragma unroll
        for (int half = 0; half < 2; half++) {
            float4 v[4];
#pragma unroll
            for (int i = 0; i < 4; i++)
                v[i] = __ldcs(&nrow[tid + ((half * 4 + i) << 8)]);
#pragma unroll
            for (int i = 0; i < 4; i++) {
                float4 w = v[i];
                float mx = fmaxf(fmaxf(w.x, w.y), fmaxf(w.z, w.w));
                if (mx > TAU) {
                    int np = (w.x > TAU) + (w.y > TAU) + (w.z > TAU) + (w.w > TAU);
                    int b = atomicAdd(&s_cnt, np);
                    int jb = (tid + ((half * 4 + i) << 8)) << 2;
                    unsigned long long cx =
                        (((unsigned long long)__float_as_uint(w.x)) << 32) | (unsigned)(jb);
                    unsigned long long cy =
                        (((unsigned long long)__float_as_uint(w.y)) << 32) | (unsigned)(jb + 1);
                    unsigned long long cz =
                        (((unsigned long long)__float_as_uint(w.z)) << 32) | (unsigned)(jb + 2);
                    unsigned long long cw =
                        (((unsigned long long)__float_as_uint(w.w)) << 32) | (unsigned)(jb + 3);
                    if (w.x > TAU) { if (b < MAXC) s_cand[b] = cx; b++; }
                    if (w.y > TAU) { if (b < MAXC) s_cand[b] = cy; b++; }
                    if (w.z > TAU) { if (b < MAXC) s_cand[b] = cz; b++; }
                    if (w.w > TAU) { if (b < MAXC) s_cand[b] = cw; b++; }
                    if (mx > HOT) {
                        int nh = (w.x > HOT) + (w.y > HOT) + (w.z > HOT) + (w.w > HOT);
                        int hb = atomicAdd(&s_hcnt, nh);
                        if (w.x > HOT) { if (hb < HMAX) s_hot[hb] = cx; hb++; }
                        if (w.y > HOT) { if (hb < HMAX) s_hot[hb] = cy; hb++; }
                        if (w.z > HOT) { if (hb < HMAX) s_hot[hb] = cz; hb++; }
                        if (w.w > HOT) { if (hb < HMAX) s_hot[hb] = cw; hb++; }
                    }
                }
            }
        }
    }
    __syncthreads();
    int cnt  = min(s_cnt, MAXC);
    int hcnt = s_hcnt;   // > HMAX triggers fallback
    unsigned ee_base = smem_u32(s_ee);

    // pivot: strictly below any key whose score beats the plateau + 0.0098.
    float c_plat = fmaxf(xla_tanh(16.0f), 0.0f);
    float pivot  = __fadd_rn(c_plat, __fmul_rn(0.01f, 0.98f));
    unsigned long long pivotKey =
        ((unsigned long long)__float_as_uint(pivot)) << 32;

    bool fast = (hcnt <= HMAX);
    if (fast) {
        // Phase 2 (hot): score only u > 0.98 candidates (~165).
        score_list(s_hot, hcnt, s_key, s_adj, s_de, s_ee, ee_base, tid, N);

        // Phase 3: pivot screen over hot keys.
        if (tid < hcnt && s_key[tid] > pivotKey) {
            int p = atomicAdd(&s_scnt, 1);
            if (p < SMAX) { s_skey[p] = s_key[tid]; s_sadj[p] = s_adj[tid]; }
        }
        __syncthreads();
        int Sc = s_scnt;
        if (Sc >= KK && Sc <= SMAX) {
            // Typical: exact rank among ~33 survivors (distinct keys).
            if (tid < Sc) {
                unsigned long long k = s_skey[tid];
                int r = 0;
                for (int m = 0; m < Sc; m++) r += (s_skey[m] > k);
                if (r < KK) {
                    sel_j[r] = (N - 1) - (int)(unsigned)k;
                    sel_w[r] = s_sadj[tid];
                }
            }
            __syncthreads();
            fast = true;
        } else {
            fast = false;
        }
        __syncthreads();
    }
    if (!fast) {
        // Rare exact fallback: score the FULL list, all-pairs rank.
        score_list(s_cand, cnt, s_key, s_adj, s_de, s_ee, ee_base, tid, N);
        unsigned long long k0 = (tid < cnt) ? s_key[tid] : 0ull;
        unsigned long long k1 = (tid + 256 < cnt) ? s_key[tid + 256] : 0ull;
        int r0 = 0, r1 = 0;
        for (int m = 0; m < cnt; m++) {
            unsigned long long km = s_key[m];
            r0 += (km > k0);
            r1 += (km > k1);
        }
        if (tid < cnt && r0 < KK) {
            sel_j[r0] = (N - 1) - (int)(unsigned)k0;
            sel_w[r0] = s_adj[tid];
        }
        if (tid + 256 < cnt && r1 < KK) {
            sel_j[r1] = (N - 1) - (int)(unsigned)k1;
            sel_w[r1] = s_adj[tid + 256];
        }
        __syncthreads();
    }

    // Phase 4: sort the 20 kept indices ascending (rank by counting).
    if (tid < KK) {
        int j = sel_j[tid];
        int rank = 0;
#pragma unroll
        for (int m = 0; m < KK; m++) rank += (sel_j[m] < j);
        srt_j[rank] = j;
        srt_w[rank] = sel_w[tid];
    }
    __syncthreads();

    // Phase 5: write outputs. [src(B*N*K) | dst(B*N*K) | HEW(B*N*K)].
    long long BNK = (long long)B * N * KK;
    if (tid < 3 * B * KK) {
        int sec = tid / (B * KK);
        int rem = tid % (B * KK);
        int b = rem / KK, k = rem % KK;
        long long pos = ((long long)b * N + row) * (long long)KK + k;
        float val;
        if      (sec == 0) val = (float)(row + b * N);
        else if (sec == 1) val = (float)(srt_j[k] + b * N);
        else               val = srt_w[k];
        long long off = (long long)sec * BNK + pos;
        if (off < out_size) out[off] = val;
    }
}

extern "C" void kernel_launch(void* const* d_in, const int* in_sizes, int n_in,
                              void* d_out, int out_size) {
    // inputs: [0]=x (unused), [1]=nodevec1, [2]=nodevec2, [3]=noise
    const float* v1    = (const float*)d_in[1];
    const float* v2    = (const float*)d_in[2];
    const float* noise = (const float*)d_in[3];
    int N = in_sizes[1] / DVEC;           // 8192
    int B = in_sizes[0] / (N * 12);       // 4
    int n = N * DVEC;

    prep_kernel<<<(n + 255) / 256, 256>>>(v1, v2, n);
    row_kernel<<<N, 256>>>(noise, (float*)d_out, N, B, (long long)out_size);
}

// round 14
// speedup vs baseline: 1.3470x; 1.3470x over previous
#include <cuda_runtime.h>
#include <cstdint>

// GCNADP: adj = relu(tanh(2 * tanh(2*nv1) @ tanh(2*nv2)^T)); top-20 per row of
// adj + 0.01*noise; emit E=[src;dst] and HEW, all as float32.
//
// Plateau filter: XLA tanh clamps at |x|=7.90531..., so ~20% of adj entries
// per row equal the same plateau constant c_plat (max attainable adj). Pivot
// screen: survivors = {score > c_plat + 0.0098}; >=20 survivors => top-20 is
// a subset of survivors, EXACT by key order. survivor => u > 0.98 (adj <=
// c_plat, fmul/fadd monotone), so only u>0.98 candidates need scoring.
//
// R14: R12 phase 1 (single TAU list - R13's dual-list push cost more than it
// saved) + hot extraction as a cheap post-pass over s_cand + screen fused
// into the scoring epilogue (no bulk key/adj writes, no screen barrier on
// the fast path). Rare rows (<20 or >64 survivors, hot overflow) take the
// exact full-list score + all-pairs rank fallback.

#define KK    20
#define MAXC  512
#define TAU   0.955f
#define HOT   0.98f
#define MAXN  8192
#define DVEC  40
#define BATCH 128
#define ESTR  44   // padded smem row stride in floats (16B multiple: 176B)
#define SMAX  64   // survivor list capacity
#define HMAX  256  // hot list capacity

__device__ __align__(16) float g_DE[MAXN * DVEC];
__device__ __align__(16) float g_EE[MAXN * DVEC];

__device__ __forceinline__ unsigned smem_u32(const void* p) {
    unsigned a;
    asm("{ .reg .u64 t; cvta.to.shared.u64 t, %1; cvt.u32.u64 %0, t; }"
        : "=r"(a) : "l"(p));
    return a;
}
__device__ __forceinline__ void cp_async16(unsigned dst, const void* src) {
    asm volatile("cp.async.ca.shared.global [%0], [%1], 16;"
                 :: "r"(dst), "l"(src));
}

// XLA EmitFastTanh (f32): clamp to +-7.90531110763549805, rational P7/Q4 with
// plain (non-contracted) mul/add, passthrough for |x| < 4e-4, IEEE division.
__device__ __forceinline__ float xla_tanh(float x) {
    float ax = fabsf(x);
    float xc = fminf(fmaxf(x, -7.90531110763549805f), 7.90531110763549805f);
    float x2 = __fmul_rn(xc, xc);
    float p = __fadd_rn(__fmul_rn(x2, -2.76076847742355e-16f), 2.00018790482477e-13f);
    p = __fadd_rn(__fmul_rn(x2, p), -8.60467152213735e-11f);
    p = __fadd_rn(__fmul_rn(x2, p),  5.12229709037114e-08f);
    p = __fadd_rn(__fmul_rn(x2, p),  1.48572235717979e-05f);
    p = __fadd_rn(__fmul_rn(x2, p),  6.37261928875436e-04f);
    p = __fadd_rn(__fmul_rn(x2, p),  4.89352455891786e-03f);
    p = __fmul_rn(xc, p);
    float q = __fadd_rn(__fmul_rn(x2, 1.19825839466702e-06f), 1.18534705686654e-04f);
    q = __fadd_rn(__fmul_rn(x2, q), 2.26843463243900e-03f);
    q = __fadd_rn(__fmul_rn(x2, q), 4.89352518554385e-03f);
    float r = __fdiv_rn(p, q);
    return (ax < 4.0e-4f) ? x : r;
}

__global__ void prep_kernel(const float* __restrict__ v1,
                            const float* __restrict__ v2, int n) {
    int i = blockIdx.x * blockDim.x + threadIdx.x;
    if (i < n) {
        g_DE[i] = xla_tanh(__fmul_rn(2.0f, v1[i]));
        g_EE[i] = xla_tanh(__fmul_rn(2.0f, v2[i]));
    }
}

// Score one candidate word [u:32|j:32] given its staged EE row (rounding
// identical to R6/R8). Returns adj and the packed selection key.
__device__ __forceinline__ void score_one(
    unsigned long long cd, const float* __restrict__ erow,
    const float* __restrict__ s_de, int N,
    float& adj, unsigned long long& key) {
    float u = __uint_as_float((unsigned)(cd >> 32));
    int j = (int)(unsigned)cd;
    const float4* e = reinterpret_cast<const float4*>(erow);
    float s = 0.0f;
#pragma unroll
    for (int q2 = 0; q2 < DVEC / 4; q2++) {
        float4 ev = e[q2];
        s = fmaf(s_de[q2 * 4 + 0], ev.x, s);
        s = fmaf(s_de[q2 * 4 + 1], ev.y, s);
        s = fmaf(s_de[q2 * 4 + 2], ev.z, s);
        s = fmaf(s_de[q2 * 4 + 3], ev.w, s);
    }
    float t = xla_tanh(__fmul_rn(2.0f, s));
    adj = fmaxf(t, 0.0f);
    float score = __fadd_rn(adj, __fmul_rn(0.01f, u));  // >= 0
    key = (((unsigned long long)__float_as_uint(score)) << 32)
        | (unsigned)(N - 1 - j);
}

// Stage a batch of candidates' EE rows into smem (2 threads x 5 cp.async of
// 16B per candidate, coalesced along each row).
__device__ __forceinline__ void stage_batch(
    const unsigned long long* __restrict__ list, int c0, int bc,
    unsigned ee_base, int tid) {
    int cl = tid >> 1, q0 = tid & 1;
    if (cl < bc) {
        int j = (int)(unsigned)list[c0 + cl];
        const float* src = g_EE + j * DVEC;
        unsigned dst = ee_base + (unsigned)(cl * ESTR) * 4u;
#pragma unroll
        for (int i = 0; i < 5; i++) {
            int q = q0 + i * 2;
            cp_async16(dst + (unsigned)q * 16u, src + q * 4);
        }
    }
    asm volatile("cp.async.commit_group;" ::: "memory");
    asm volatile("cp.async.wait_group 0;" ::: "memory");
}

// One block per row: stream row -> candidate list -> hot compact -> score hot
// with fused survivor push -> tiny exact rank (rare exact fallback) -> write.
__global__ __launch_bounds__(256, 6) void row_kernel(
    const float* __restrict__ noise, float* __restrict__ out,
    int N, int B, long long out_size) {
    int row = blockIdx.x;
    int tid = threadIdx.x;

    __shared__ alignas(16) float s_ee[BATCH * ESTR];  // staged EE rows (22KB)
    __shared__ alignas(16) float s_de[DVEC];
    __shared__ int   s_cnt, s_hcnt, s_scnt;
    __shared__ unsigned long long s_cand[MAXC];       // full list [u:32|j:32]
    __shared__ unsigned long long s_hot[HMAX];        // hot list  (u > 0.98)
    __shared__ unsigned long long s_key[MAXC];        // fallback only
    __shared__ float s_adj[MAXC];                     // fallback only
    __shared__ unsigned long long s_skey[SMAX];
    __shared__ float s_sadj[SMAX];
    __shared__ int   sel_j[KK];
    __shared__ float sel_w[KK];
    __shared__ int   srt_j[KK];
    __shared__ float srt_w[KK];

    if (tid < DVEC) s_de[tid] = g_DE[row * DVEC + tid];
    if (tid == 0) { s_cnt = 0; s_hcnt = 0; s_scnt = 0; }
    __syncthreads();

    // Phase 1: stream this row (two rounds of 4 float4/thread), filter
    // u > TAU into smem candidate list with a max4 early-out. (R12 form.)
    {
        const float4* nrow =
            reinterpret_cast<const float4*>(noise + (size_t)row * N);
#pragma unroll
        for (int half = 0; half < 2; half++) {
            float4 v[4];
#pragma unroll
            for (int i = 0; i < 4; i++)
                v[i] = __ldcs(&nrow[tid + ((half * 4 + i) << 8)]);
#pragma unroll
            for (int i = 0; i < 4; i++) {
                float4 w = v[i];
                float mx = fmaxf(fmaxf(w.x, w.y), fmaxf(w.z, w.w));
                if (mx > TAU) {
                    int np = (w.x > TAU) + (w.y > TAU) + (w.z > TAU) + (w.w > TAU);
                    int b = atomicAdd(&s_cnt, np);
                    int jb = (tid + ((half * 4 + i) << 8)) << 2;
                    if (w.x > TAU) { if (b < MAXC) s_cand[b] = (((unsigned long long)__float_as_uint(w.x)) << 32) | (unsigned)(jb);     b++; }
                    if (w.y > TAU) { if (b < MAXC) s_cand[b] = (((unsigned long long)__float_as_uint(w.y)) << 32) | (unsigned)(jb + 1); b++; }
                    if (w.z > TAU) { if (b < MAXC) s_cand[b] = (((unsigned long long)__float_as_uint(w.z)) << 32) | (unsigned)(jb + 2); b++; }
                    if (w.w > TAU) { if (b < MAXC) s_cand[b] = (((unsigned long long)__float_as_uint(w.w)) << 32) | (unsigned)(jb + 3); b++; }
                }
            }
        }
    }
    __syncthreads();
    int cnt = min(s_cnt, MAXC);
    unsigned ee_base = smem_u32(s_ee);

    // Hot compact: survivors require u > 0.98, so pull only those from the
    // candidate list (u bits live in the packed high word; positive floats
    // compare monotonically as unsigned).
    {
        unsigned hotbits = __float_as_uint(HOT);
#pragma unroll
        for (int h = 0; h < 2; h++) {
            int c = tid + (h << 8);
            if (c < cnt) {
                unsigned long long cd = s_cand[c];
                if ((unsigned)(cd >> 32) > hotbits) {
                    int p = atomicAdd(&s_hcnt, 1);
                    if (p < HMAX) s_hot[p] = cd;
                }
            }
        }
    }
    __syncthreads();
    int hcnt = s_hcnt;

    // pivot: strictly below any key whose score beats the plateau + 0.0098.
    float c_plat = fmaxf(xla_tanh(16.0f), 0.0f);
    float pivot  = __fadd_rn(c_plat, __fmul_rn(0.01f, 0.98f));

    bool fast = (hcnt <= HMAX);
    if (fast) {
        // Score hot candidates; fused screen pushes survivors immediately.
        int nb = (hcnt + BATCH - 1) / BATCH;
        for (int b = 0; b < nb; b++) {
            int c0 = b * BATCH;
            int bc = min(BATCH, hcnt - c0);
            stage_batch(s_hot, c0, bc, ee_base, tid);
            __syncthreads();
            if (tid < bc) {
                float adj; unsigned long long key;
                score_one(s_hot[c0 + tid], s_ee + tid * ESTR, s_de, N, adj, key);
                float score = __uint_as_float((unsigned)(key >> 32));
                if (score > pivot) {
                    int p = atomicAdd(&s_scnt, 1);
                    if (p < SMAX) { s_skey[p] = key; s_sadj[p] = adj; }
                }
            }
            __syncthreads();
        }
        int Sc = s_scnt;
        if (Sc >= KK && Sc <= SMAX) {
            // Typical: exact rank among ~33 survivors (distinct keys). With
            // Sc >= 20 strict survivors, any score==pivot key ranks below
            // them all, so top-20 is inside the strict-survivor set.
            if (tid < Sc) {
                unsigned long long k = s_skey[tid];
                int r = 0;
                for (int m = 0; m < Sc; m++) r += (s_skey[m] > k);
                if (r < KK) {
                    sel_j[r] = (N - 1) - (int)(unsigned)k;
                    sel_w[r] = s_sadj[tid];
                }
            }
        } else {
            fast = false;
        }
        __syncthreads();
    }
    if (!fast) {
        // Rare exact fallback: score the FULL list, all-pairs rank.
        int nb = (cnt + BATCH - 1) / BATCH;
        for (int b = 0; b < nb; b++) {
            int c0 = b * BATCH;
            int bc = min(BATCH, cnt - c0);
            stage_batch(s_cand, c0, bc, ee_base, tid);
            __syncthreads();
            if (tid < bc) {
                float adj; unsigned long long key;
                score_one(s_cand[c0 + tid], s_ee + tid * ESTR, s_de, N, adj, key);
                s_adj[c0 + tid] = adj;
                s_key[c0 + tid] = key;
            }
            __syncthreads();
        }
        unsigned long long k0 = (tid < cnt) ? s_key[tid] : 0ull;
        unsigned long long k1 = (tid + 256 < cnt) ? s_key[tid + 256] : 0ull;
        int r0 = 0, r1 = 0;
        for (int m = 0; m < cnt; m++) {
            unsigned long long km = s_key[m];
            r0 += (km > k0);
            r1 += (km > k1);
        }
        if (tid < cnt && r0 < KK) {
            sel_j[r0] = (N - 1) - (int)(unsigned)k0;
            sel_w[r0] = s_adj[tid];
        }
        if (tid + 256 < cnt && r1 < KK) {
            sel_j[r1] = (N - 1) - (int)(unsigned)k1;
            sel_w[r1] = s_adj[tid + 256];
        }
        __syncthreads();
    }

    // Sort the 20 kept indices ascending (rank by counting).
    if (tid < KK) {
        int j = sel_j[tid];
        int rank = 0;
#pragma unroll
        for (int m = 0; m < KK; m++) rank += (sel_j[m] < j);
        srt_j[rank] = j;
        srt_w[rank] = sel_w[tid];
    }
    __syncthreads();

    // Write outputs. [src(B*N*K) | dst(B*N*K) | HEW(B*N*K)].
    long long BNK = (long long)B * N * KK;
    if (tid < 3 * B * KK) {
        int sec = tid / (B * KK);
        int rem = tid % (B * KK);
        int b = rem / KK, k = rem % KK;
        long long pos = ((long long)b * N + row) * (long long)KK + k;
        float val;
        if      (sec == 0) val = (float)(row + b * N);
        else if (sec == 1) val = (float)(srt_j[k] + b * N);
        else               val = srt_w[k];
        long long off = (long long)sec * BNK + pos;
        if (off < out_size) out[off] = val;
    }
}

extern "C" void kernel_launch(void* const* d_in, const int* in_sizes, int n_in,
                              void* d_out, int out_size) {
    // inputs: [0]=x (unused), [1]=nodevec1, [2]=nodevec2, [3]=noise
    const float* v1    = (const float*)d_in[1];
    const float* v2    = (const float*)d_in[2];
    const float* noise = (const float*)d_in[3];
    int N = in_sizes[1] / DVEC;           // 8192
    int B = in_sizes[0] / (N * 12);       // 4
    int n = N * DVEC;

    prep_kernel<<<(n + 255) / 256, 256>>>(v1, v2, n);
    row_kernel<<<N, 256>>>(noise, (float*)d_out, N, B, (long long)out_size);
}

// round 15
// speedup vs baseline: 1.5654x; 1.1621x over previous
#include <cuda_runtime.h>
#include <cstdint>

// GCNADP: adj = relu(tanh(2 * tanh(2*nv1) @ tanh(2*nv2)^T)); top-20 per row of
// adj + 0.01*noise; emit E=[src;dst] and HEW, all as float32.
//
// Plateau filter: XLA tanh clamps at |x|=7.90531..., so ~20% of adj entries
// per row equal the same plateau constant c_plat (max attainable adj). Pivot
// screen: survivors = {score > c_plat + 0.0098}; >=20 survivors => top-20 is
// a subset of survivors, EXACT by key order. survivor => u > 0.98 (adj <=
// c_plat, fmul/fadd monotone), so only u>0.98 candidates need scoring.
//
// R15: phase 1 collects ONLY u > 0.98 (~165/row; 7.8% of float4 groups) --
// that is everything the fast path scores. Deletes the TAU compare chains,
// ~205 extra pushes, and R14's hot-compact pass (512 LDS + atomics +
// barrier). Rare fallback rows (<20 survivors or hot overflow, ~1-2%)
// re-stream their 32KB noise row to rebuild the u>0.955 list, score it all,
// and take the exact all-pairs rank.

#define KK    20
#define MAXC  512
#define TAU   0.955f
#define HOT   0.98f
#define MAXN  8192
#define DVEC  40
#define BATCH 128
#define ESTR  44   // padded smem row stride in floats (16B multiple: 176B)
#define SMAX  64   // survivor list capacity
#define HMAX  256  // hot candidate list capacity

__device__ __align__(16) float g_DE[MAXN * DVEC];
__device__ __align__(16) float g_EE[MAXN * DVEC];

__device__ __forceinline__ unsigned smem_u32(const void* p) {
    unsigned a;
    asm("{ .reg .u64 t; cvta.to.shared.u64 t, %1; cvt.u32.u64 %0, t; }"
        : "=r"(a) : "l"(p));
    return a;
}
__device__ __forceinline__ void cp_async16(unsigned dst, const void* src) {
    asm volatile("cp.async.ca.shared.global [%0], [%1], 16;"
                 :: "r"(dst), "l"(src));
}

// XLA EmitFastTanh (f32): clamp to +-7.90531110763549805, rational P7/Q4 with
// plain (non-contracted) mul/add, passthrough for |x| < 4e-4, IEEE division.
__device__ __forceinline__ float xla_tanh(float x) {
    float ax = fabsf(x);
    float xc = fminf(fmaxf(x, -7.90531110763549805f), 7.90531110763549805f);
    float x2 = __fmul_rn(xc, xc);
    float p = __fadd_rn(__fmul_rn(x2, -2.76076847742355e-16f), 2.00018790482477e-13f);
    p = __fadd_rn(__fmul_rn(x2, p), -8.60467152213735e-11f);
    p = __fadd_rn(__fmul_rn(x2, p),  5.12229709037114e-08f);
    p = __fadd_rn(__fmul_rn(x2, p),  1.48572235717979e-05f);
    p = __fadd_rn(__fmul_rn(x2, p),  6.37261928875436e-04f);
    p = __fadd_rn(__fmul_rn(x2, p),  4.89352455891786e-03f);
    p = __fmul_rn(xc, p);
    float q = __fadd_rn(__fmul_rn(x2, 1.19825839466702e-06f), 1.18534705686654e-04f);
    q = __fadd_rn(__fmul_rn(x2, q), 2.26843463243900e-03f);
    q = __fadd_rn(__fmul_rn(x2, q), 4.89352518554385e-03f);
    float r = __fdiv_rn(p, q);
    return (ax < 4.0e-4f) ? x : r;
}

__global__ void prep_kernel(const float* __restrict__ v1,
                            const float* __restrict__ v2, int n) {
    int i = blockIdx.x * blockDim.x + threadIdx.x;
    if (i < n) {
        g_DE[i] = xla_tanh(__fmul_rn(2.0f, v1[i]));
        g_EE[i] = xla_tanh(__fmul_rn(2.0f, v2[i]));
    }
}

// Score one candidate word [u:32|j:32] given its staged EE row (rounding
// identical to R6/R8). Returns adj and the packed selection key.
__device__ __forceinline__ void score_one(
    unsigned long long cd, const float* __restrict__ erow,
    const float* __restrict__ s_de, int N,
    float& adj, unsigned long long& key) {
    float u = __uint_as_float((unsigned)(cd >> 32));
    int j = (int)(unsigned)cd;
    const float4* e = reinterpret_cast<const float4*>(erow);
    float s = 0.0f;
#pragma unroll
    for (int q2 = 0; q2 < DVEC / 4; q2++) {
        float4 ev = e[q2];
        s = fmaf(s_de[q2 * 4 + 0], ev.x, s);
        s = fmaf(s_de[q2 * 4 + 1], ev.y, s);
        s = fmaf(s_de[q2 * 4 + 2], ev.z, s);
        s = fmaf(s_de[q2 * 4 + 3], ev.w, s);
    }
    float t = xla_tanh(__fmul_rn(2.0f, s));
    adj = fmaxf(t, 0.0f);
    float score = __fadd_rn(adj, __fmul_rn(0.01f, u));  // >= 0
    key = (((unsigned long long)__float_as_uint(score)) << 32)
        | (unsigned)(N - 1 - j);
}

// Stage a batch of candidates' EE rows into smem (2 threads x 5 cp.async of
// 16B per candidate, coalesced along each row).
__device__ __forceinline__ void stage_batch(
    const unsigned long long* __restrict__ list, int c0, int bc,
    unsigned ee_base, int tid) {
    int cl = tid >> 1, q0 = tid & 1;
    if (cl < bc) {
        int j = (int)(unsigned)list[c0 + cl];
        const float* src = g_EE + j * DVEC;
        unsigned dst = ee_base + (unsigned)(cl * ESTR) * 4u;
#pragma unroll
        for (int i = 0; i < 5; i++) {
            int q = q0 + i * 2;
            cp_async16(dst + (unsigned)q * 16u, src + q * 4);
        }
    }
    asm volatile("cp.async.commit_group;" ::: "memory");
    asm volatile("cp.async.wait_group 0;" ::: "memory");
}

// One block per row: stream row (u>HOT only) -> score with fused survivor
// push -> tiny exact rank. Rare fallback: re-stream row at u>TAU, score all,
// all-pairs rank. Then sort by j and write.
__global__ __launch_bounds__(256, 6) void row_kernel(
    const float* __restrict__ noise, float* __restrict__ out,
    int N, int B, long long out_size) {
    int row = blockIdx.x;
    int tid = threadIdx.x;

    __shared__ alignas(16) float s_ee[BATCH * ESTR];  // staged EE rows (22KB)
    __shared__ alignas(16) float s_de[DVEC];
    __shared__ int   s_hcnt, s_scnt, s_fcnt;
    __shared__ unsigned long long s_hot[HMAX];        // u > 0.98 candidates
    __shared__ unsigned long long s_key[MAXC];        // fallback list / keys
    __shared__ float s_adj[MAXC];                     // fallback adj
    __shared__ unsigned long long s_skey[SMAX];
    __shared__ float s_sadj[SMAX];
    __shared__ int   sel_j[KK];
    __shared__ float sel_w[KK];
    __shared__ int   srt_j[KK];
    __shared__ float srt_w[KK];

    if (tid < DVEC) s_de[tid] = g_DE[row * DVEC + tid];
    if (tid == 0) { s_hcnt = 0; s_scnt = 0; s_fcnt = 0; }
    __syncthreads();

    const float4* nrow =
        reinterpret_cast<const float4*>(noise + (size_t)row * N);

    // Phase 1: stream this row (two rounds of 4 float4/thread); push ONLY
    // u > HOT candidates (everything the fast path scores).
    {
#pragma unroll
        for (int half = 0; half < 2; half++) {
            float4 v[4];
#pragma unroll
            for (int i = 0; i < 4; i++)
                v[i] = __ldcs(&nrow[tid + ((half * 4 + i) << 8)]);
#pragma unroll
            for (int i = 0; i < 4; i++) {
                float4 w = v[i];
                float mx = fmaxf(fmaxf(w.x, w.y), fmaxf(w.z, w.w));
                if (mx > HOT) {
                    int np = (w.x > HOT) + (w.y > HOT) + (w.z > HOT) + (w.w > HOT);
                    int b = atomicAdd(&s_hcnt, np);
                    int jb = (tid + ((half * 4 + i) << 8)) << 2;
                    if (w.x > HOT) { if (b < HMAX) s_hot[b] = (((unsigned long long)__float_as_uint(w.x)) << 32) | (unsigned)(jb);     b++; }
                    if (w.y > HOT) { if (b < HMAX) s_hot[b] = (((unsigned long long)__float_as_uint(w.y)) << 32) | (unsigned)(jb + 1); b++; }
                    if (w.z > HOT) { if (b < HMAX) s_hot[b] = (((unsigned long long)__float_as_uint(w.z)) << 32) | (unsigned)(jb + 2); b++; }
                    if (w.w > HOT) { if (b < HMAX) s_hot[b] = (((unsigned long long)__float_as_uint(w.w)) << 32) | (unsigned)(jb + 3); b++; }
                }
            }
        }
    }
    __syncthreads();
    int hcnt = s_hcnt;
    unsigned ee_base = smem_u32(s_ee);

    // pivot: strictly below any key whose score beats the plateau + 0.0098.
    float c_plat = fmaxf(xla_tanh(16.0f), 0.0f);
    float pivot  = __fadd_rn(c_plat, __fmul_rn(0.01f, 0.98f));

    bool fast = (hcnt <= HMAX);
    if (fast) {
        // Score hot candidates; fused screen pushes survivors immediately.
        int nb = (hcnt + BATCH - 1) / BATCH;
        for (int b = 0; b < nb; b++) {
            int c0 = b * BATCH;
            int bc = min(BATCH, hcnt - c0);
            stage_batch(s_hot, c0, bc, ee_base, tid);
            __syncthreads();
            if (tid < bc) {
                float adj; unsigned long long key;
                score_one(s_hot[c0 + tid], s_ee + tid * ESTR, s_de, N, adj, key);
                float score = __uint_as_float((unsigned)(key >> 32));
                if (score > pivot) {
                    int p = atomicAdd(&s_scnt, 1);
                    if (p < SMAX) { s_skey[p] = key; s_sadj[p] = adj; }
                }
            }
            __syncthreads();
        }
        int Sc = s_scnt;
        if (Sc >= KK && Sc <= SMAX) {
            // Typical: exact rank among ~33 survivors (distinct keys). With
            // Sc >= 20 strict survivors, any score==pivot key ranks below
            // them all, so top-20 is inside the strict-survivor set.
            if (tid < Sc) {
                unsigned long long k = s_skey[tid];
                int r = 0;
                for (int m = 0; m < Sc; m++) r += (s_skey[m] > k);
                if (r < KK) {
                    sel_j[r] = (N - 1) - (int)(unsigned)k;
                    sel_w[r] = s_sadj[tid];
                }
            }
        } else {
            fast = false;
        }
        __syncthreads();
    }
    if (!fast) {
        // Rare exact fallback: re-stream the row, collect u > TAU into
        // s_key (doubling as the candidate list), score all, all-pairs rank.
        for (int g = tid; g < (N >> 2); g += 256) {
            float4 w = __ldcs(&nrow[g]);
            float mx = fmaxf(fmaxf(w.x, w.y), fmaxf(w.z, w.w));
            if (mx > TAU) {
                int np = (w.x > TAU) + (w.y > TAU) + (w.z > TAU) + (w.w > TAU);
                int b = atomicAdd(&s_fcnt, np);
                int jb = g << 2;
                if (w.x > TAU) { if (b < MAXC) s_key[b] = (((unsigned long long)__float_as_uint(w.x)) << 32) | (unsigned)(jb);     b++; }
                if (w.y > TAU) { if (b < MAXC) s_key[b] = (((unsigned long long)__float_as_uint(w.y)) << 32) | (unsigned)(jb + 1); b++; }
                if (w.z > TAU) { if (b < MAXC) s_key[b] = (((unsigned long long)__float_as_uint(w.z)) << 32) | (unsigned)(jb + 2); b++; }
                if (w.w > TAU) { if (b < MAXC) s_key[b] = (((unsigned long long)__float_as_uint(w.w)) << 32) | (unsigned)(jb + 3); b++; }
            }
        }
        __syncthreads();
        int cnt = min(s_fcnt, MAXC);
        // Score in place: each slot is read (stage + score) before being
        // overwritten by its own thread's key write.
        int nb = (cnt + BATCH - 1) / BATCH;
        for (int b = 0; b < nb; b++) {
            int c0 = b * BATCH;
            int bc = min(BATCH, cnt - c0);
            stage_batch(s_key, c0, bc, ee_base, tid);
            __syncthreads();
            if (tid < bc) {
                float adj; unsigned long long key;
                score_one(s_key[c0 + tid], s_ee + tid * ESTR, s_de, N, adj, key);
                s_adj[c0 + tid] = adj;
                s_key[c0 + tid] = key;
            }
            __syncthreads();
        }
        unsigned long long k0 = (tid < cnt) ? s_key[tid] : 0ull;
        unsigned long long k1 = (tid + 256 < cnt) ? s_key[tid + 256] : 0ull;
        int r0 = 0, r1 = 0;
        for (int m = 0; m < cnt; m++) {
            unsigned long long km = s_key[m];
            r0 += (km > k0);
            r1 += (km > k1);
        }
        if (tid < cnt && r0 < KK) {
            sel_j[r0] = (N - 1) - (int)(unsigned)k0;
            sel_w[r0] = s_adj[tid];
        }
        if (tid + 256 < cnt && r1 < KK) {
            sel_j[r1] = (N - 1) - (int)(unsigned)k1;
            sel_w[r1] = s_adj[tid + 256];
        }
        __syncthreads();
    }

    // Sort the 20 kept indices ascending (rank by counting).
    if (tid < KK) {
        int j = sel_j[tid];
        int rank = 0;
#pragma unroll
        for (int m = 0; m < KK; m++) rank += (sel_j[m] < j);
        srt_j[rank] = j;
        srt_w[rank] = sel_w[tid];
    }
    __syncthreads();

    // Write outputs. [src(B*N*K) | dst(B*N*K) | HEW(B*N*K)].
    long long BNK = (long long)B * N * KK;
    if (tid < 3 * B * KK) {
        int sec = tid / (B * KK);
        int rem = tid % (B * KK);
        int b = rem / KK, k = rem % KK;
        long long pos = ((long long)b * N + row) * (long long)KK + k;
        float val;
        if      (sec == 0) val = (float)(row + b * N);
        else if (sec == 1) val = (float)(srt_j[k] + b * N);
        else               val = srt_w[k];
        long long off = (long long)sec * BNK + pos;
        if (off < out_size) out[off] = val;
    }
}

extern "C" void kernel_launch(void* const* d_in, const int* in_sizes, int n_in,
                              void* d_out, int out_size) {
    // inputs: [0]=x (unused), [1]=nodevec1, [2]=nodevec2, [3]=noise
    const float* v1    = (const float*)d_in[1];
    const float* v2    = (const float*)d_in[2];
    const float* noise = (const float*)d_in[3];
    int N = in_sizes[1] / DVEC;           // 8192
    int B = in_sizes[0] / (N * 12);       // 4
    int n = N * DVEC;

    prep_kernel<<<(n + 255) / 256, 256>>>(v1, v2, n);
    row_kernel<<<N, 256>>>(noise, (float*)d_out, N, B, (long long)out_size);
}